// round 5
// baseline (speedup 1.0000x reference)
#include <cuda_runtime.h>
#include <math.h>

#define HIDDEN   2048
#define NQ       8
#define HD       256
#define QKV_ROWS 2560   // (8 + 2) * 256
#define SEQ      8192
#define LAYER    5
#define CHUNK    32
#define NCHUNK   256    // SEQ / CHUNK
#define GEMV_GRID 296   // 2 blocks per SM, persistent

// ---------------- scratch (device globals; no allocation) ----------------
__device__ float g_qkv[QKV_ROWS];              // raw qkv projection
__device__ float g_part[NCHUNK * NQ * HD];     // per-chunk partial P.V
__device__ float g_l[NCHUNK * NQ];             // per-chunk exp-sums
__device__ float g_attn[NQ * HD];              // combined attention output

__device__ __forceinline__ float warp_sum(float v) {
#pragma unroll
    for (int o = 16; o; o >>= 1) v += __shfl_xor_sync(0xffffffffu, v, o);
    return v;
}
__device__ __forceinline__ float warp_max(float v) {
#pragma unroll
    for (int o = 16; o; o >>= 1) v = fmaxf(v, __shfl_xor_sync(0xffffffffu, v, o));
    return v;
}

__device__ __forceinline__ float dot4(float4 a, float4 b) {
    return a.x * b.x + a.y * b.y + a.z * b.z + a.w * b.w;
}

// ---------------- persistent pipelined GEMV --------------------------------
// 2 rows per iteration (128 threads/row, 4 float4/thread). Double-buffered
// W registers: next row-pair's loads are in flight while the current pair
// is reduced, so the memory pipe never drains between row-pairs.
__global__ void gemv_kernel(const float* __restrict__ W,
                            const float* __restrict__ x,
                            float* __restrict__ y, int rowPairs) {
    __shared__ float4 sx[HIDDEN / 4];
    __shared__ float swarp[2][8];
    int tid = threadIdx.x;
    const float4* x4 = reinterpret_cast<const float4*>(x);
    sx[tid]       = x4[tid];
    sx[tid + 256] = x4[tid + 256];
    __syncthreads();

    int rl   = tid >> 7;          // row within pair (0..1)
    int t    = tid & 127;         // thread within row
    int warp = tid >> 5, lane = tid & 31;
    int stride = gridDim.x;

    float4 v0 = sx[t], v1 = sx[t + 128], v2 = sx[t + 256], v3 = sx[t + 384];

    int rp = blockIdx.x;
    float4 wa0, wa1, wa2, wa3, wb0, wb1, wb2, wb3;
    {
        const float4* Wr = reinterpret_cast<const float4*>(W + (size_t)(rp * 2 + rl) * HIDDEN);
        wa0 = Wr[t]; wa1 = Wr[t + 128]; wa2 = Wr[t + 256]; wa3 = Wr[t + 384];
    }

    while (true) {
        // prefetch slot B
        int rpn = rp + stride;
        if (rpn < rowPairs) {
            const float4* Wr = reinterpret_cast<const float4*>(W + (size_t)(rpn * 2 + rl) * HIDDEN);
            wb0 = Wr[t]; wb1 = Wr[t + 128]; wb2 = Wr[t + 256]; wb3 = Wr[t + 384];
        }
        // compute slot A
        {
            float acc = dot4(wa0, v0) + dot4(wa1, v1) + dot4(wa2, v2) + dot4(wa3, v3);
            acc = warp_sum(acc);
            if (lane == 0) swarp[0][warp] = acc;
            __syncthreads();
            if (tid < 2)
                y[rp * 2 + tid] = swarp[0][4 * tid] + swarp[0][4 * tid + 1] +
                                  swarp[0][4 * tid + 2] + swarp[0][4 * tid + 3];
        }
        if (rpn >= rowPairs) break;
        rp = rpn;

        // prefetch slot A
        int rpn2 = rp + stride;
        if (rpn2 < rowPairs) {
            const float4* Wr = reinterpret_cast<const float4*>(W + (size_t)(rpn2 * 2 + rl) * HIDDEN);
            wa0 = Wr[t]; wa1 = Wr[t + 128]; wa2 = Wr[t + 256]; wa3 = Wr[t + 384];
        }
        // compute slot B
        {
            float acc = dot4(wb0, v0) + dot4(wb1, v1) + dot4(wb2, v2) + dot4(wb3, v3);
            acc = warp_sum(acc);
            if (lane == 0) swarp[1][warp] = acc;
            __syncthreads();
            if (tid < 2)
                y[rp * 2 + tid] = swarp[1][4 * tid] + swarp[1][4 * tid + 1] +
                                  swarp[1][4 * tid + 2] + swarp[1][4 * tid + 3];
        }
        if (rpn2 >= rowPairs) break;
        rp = rpn2;
    }
}

// ---------------- fused attention: norm+rope + scores + exp + partial PV ---
// One-pass flash decode: softcap bounds scores to [-50,50] so exp never
// overflows -> no running max needed. Block c owns positions [c*32,(c+1)*32).
__global__ void fused_attn_kernel(const float* __restrict__ kc,
                                  const float* __restrict__ vc,
                                  const float* __restrict__ mask,
                                  const float* __restrict__ cosv,
                                  const float* __restrict__ sinv,
                                  const float* __restrict__ qw,
                                  const float* __restrict__ kw,
                                  const int* __restrict__ kvidx) {
    __shared__ float sq[NQ * HD];      // normalized+rope+scaled Q, head-major
    __shared__ float sk[HD];           // normalized+rope K (new cache row)
    __shared__ float sexp[CHUNK * NQ]; // exp'd scores [sl][h]
    __shared__ float smask[CHUNK];
    __shared__ int   sany;

    int c    = blockIdx.x;
    int tid  = threadIdx.x;
    int warp = tid >> 5, lane = tid & 31;
    int s0   = c * CHUNK;

    // --- phase 0: fully-masked chunks exit immediately --------------------
    if (tid == 0) sany = 0;
    __syncthreads();
    if (tid < CHUNK) {
        float m = mask[s0 + tid];
        smask[tid] = m;
        if (m > -1e8f) atomicOr(&sany, 1);
    }
    __syncthreads();
    if (!sany) {
        if (tid < NQ) g_l[c * NQ + tid] = 0.0f;
        return;
    }

    // --- phase 1: norm + rope (recomputed per block; L2-resident, tiny) ---
    for (int head = warp; head < 9; head += 8) {
        float x[8];
#pragma unroll
        for (int j = 0; j < 8; j++) x[j] = g_qkv[head * HD + lane + 32 * j];
        float mv = 0.f;
#pragma unroll
        for (int j = 0; j < 8; j++) mv = fmaxf(mv, fabsf(x[j]));
        mv = warp_max(mv);
        mv = fmaxf(mv, 5.9604644775390625e-8f);   // 2^-24
        float ss = 0.f, xs[8];
#pragma unroll
        for (int j = 0; j < 8; j++) { xs[j] = x[j] / mv; ss += xs[j] * xs[j]; }
        ss = warp_sum(ss);
        float rs = rsqrtf(ss);
        const float* wv = (head < NQ) ? qw : kw;
        float y[8];
#pragma unroll
        for (int j = 0; j < 8; j++) {
            int d = lane + 32 * j;
            y[j] = rs * 16.0f * xs[j] * (1.0f + wv[d]);
        }
#pragma unroll
        for (int j = 0; j < 8; j++) {
            int d = lane + 32 * j;
            float rot = (j < 4) ? -y[j ^ 4] : y[j ^ 4];
            float out = y[j] * cosv[d] + rot * sinv[d];
            if (head < NQ) sq[head * HD + d] = out * 0.0625f;  // * 256^-0.5
            else           sk[d] = out;
        }
    }
    __syncthreads();

    int pos = *kvidx;
    const float* kbase = kc + (size_t)LAYER * SEQ * HD;

    // --- phase 2: scores -> softcap -> exp (warp per 4 positions) ---------
    {
        float acc[4][NQ];
        const float4* k4p[4];
#pragma unroll
        for (int r = 0; r < 4; r++) {
            int sl = warp * 4 + r;
            int s = s0 + sl;
            const float* krow = (s == pos) ? sk : (kbase + (size_t)s * HD);
            k4p[r] = reinterpret_cast<const float4*>(krow);
#pragma unroll
            for (int h = 0; h < NQ; h++) acc[r][h] = 0.f;
        }
#pragma unroll
        for (int i = 0; i < 2; i++) {
            int idx = i * 32 + lane;
            float4 kv[4];
#pragma unroll
            for (int r = 0; r < 4; r++) kv[r] = k4p[r][idx];
#pragma unroll
            for (int h = 0; h < NQ; h++) {
                const float4* q4 = reinterpret_cast<const float4*>(&sq[h * HD]);
                float4 qv = q4[idx];
#pragma unroll
                for (int r = 0; r < 4; r++)
                    acc[r][h] += dot4(kv[r], qv);
            }
        }
#pragma unroll
        for (int r = 0; r < 4; r++) {
            int sl = warp * 4 + r;
            float m = smask[sl];
#pragma unroll
            for (int h = 0; h < NQ; h++) {
                float v = warp_sum(acc[r][h]);
                if (lane == h)
                    sexp[sl * NQ + h] = (m < -1e8f) ? 0.0f
                                      : expf(tanhf(v * 0.02f) * 50.0f + m);
            }
        }
    }
    __syncthreads();

    // --- phase 3: per-head exp-sum (warp h reduces column h) --------------
    if (warp < NQ) {
        int h = warp;
        float l = sexp[lane * NQ + h];         // CHUNK == 32 rows
        l = warp_sum(l);
        if (lane == 0) g_l[c * NQ + h] = l;
    }

    // --- phase 4: partial P.V (thread = dim d), deep unroll for MLP -------
    const float* vbase = vc + (size_t)LAYER * SEQ * HD;
    const float* vnew  = g_qkv + 9 * HD;       // xv row of qkv projection
    int d = tid;
    float acc[NQ] = {0, 0, 0, 0, 0, 0, 0, 0};
#pragma unroll 8
    for (int sl = 0; sl < CHUNK; sl++) {
        int s = s0 + sl;
        float v = (s == pos) ? vnew[d] : vbase[(size_t)s * HD + d];
#pragma unroll
        for (int h = 0; h < NQ; h++) acc[h] += sexp[sl * NQ + h] * v;
    }
#pragma unroll
    for (int h = 0; h < NQ; h++)
        g_part[(c * NQ + h) * HD + d] = acc[h];
}

// ---------------- combine partials across chunks ---------------------------
// grid = (NQ, 4). l-table preloaded to smem so the g_part loads are
// dependency-free predicated loads (batch under unroll).
__global__ void combine_kernel() {
    int h  = blockIdx.x;
    int d0 = blockIdx.y * 64;
    int tid = threadIdx.x;
    int q = tid >> 6, dl = tid & 63;
    int d = d0 + dl;

    __shared__ float sl[NCHUNK];
    sl[tid] = g_l[tid * NQ + h];
    __syncthreads();

    float acc = 0.f, L = 0.f;
#pragma unroll 16
    for (int k = 0; k < NCHUNK / 4; k++) {
        int c = q + 4 * k;
        float l = sl[c];
        if (l > 0.f) {
            L += l;
            acc += g_part[(c * NQ + h) * HD + d];
        }
    }
    __shared__ float sacc[4][64];
    __shared__ float sLr[4][64];
    sacc[q][dl] = acc;
    sLr[q][dl]  = L;
    __syncthreads();
    if (q == 0) {
        acc = sacc[0][dl] + sacc[1][dl] + sacc[2][dl] + sacc[3][dl];
        L   = sLr[0][dl] + sLr[1][dl] + sLr[2][dl] + sLr[3][dl];
        g_attn[h * HD + d] = acc / L;
    }
}

// ---------------- launch ----------------------------------------------------
extern "C" void kernel_launch(void* const* d_in, const int* in_sizes, int n_in,
                              void* d_out, int out_size) {
    const float* hs   = (const float*)d_in[0];   // hidden_states (2048)
    const float* cosv = (const float*)d_in[1];   // cos (256)
    const float* sinv = (const float*)d_in[2];   // sin (256)
    const int*   kvix = (const int*)  d_in[3];   // kv_write_indices (1)
    const float* kc   = (const float*)d_in[4];   // k_cache
    const float* vc   = (const float*)d_in[5];   // v_cache
    const float* mask = (const float*)d_in[6];   // mask (8192)
    const float* qkvw = (const float*)d_in[7];   // qkv_w (2560x2048)
    const float* ow   = (const float*)d_in[8];   // o_w   (2048x2048)
    const float* qnw  = (const float*)d_in[9];   // q_norm_w (256)
    const float* knw  = (const float*)d_in[10];  // k_norm_w (256)
    float* out = (float*)d_out;

    void* p_qkv = nullptr;
    void* p_attn = nullptr;
    cudaGetSymbolAddress(&p_qkv, g_qkv);
    cudaGetSymbolAddress(&p_attn, g_attn);

    gemv_kernel<<<GEMV_GRID, 256>>>(qkvw, hs, (float*)p_qkv, QKV_ROWS / 2);
    fused_attn_kernel<<<NCHUNK, 256>>>(kc, vc, mask, cosv, sinv, qnw, knw, kvix);
    combine_kernel<<<dim3(NQ, 4), 256>>>();
    gemv_kernel<<<GEMV_GRID, 256>>>(ow, (const float*)p_attn, out, HIDDEN / 2);
}